// round 5
// baseline (speedup 1.0000x reference)
#include <cuda_runtime.h>
#include <cuda_bf16.h>
#include <cfloat>
#include <cstdint>
#include <cstddef>

#define BATCH 16
#define SEQ   2048
#define DIM   64
#define KTOP  128

// 268 MB each: sim[b][q][k] and its transpose simT[b][k][q]
__device__ float g_sim [(size_t)BATCH * SEQ * SEQ];
__device__ float g_simT[(size_t)BATCH * SEQ * SEQ];

// Order-preserving float <-> uint key (larger float => larger key)
__device__ __forceinline__ unsigned f2key(float f) {
    unsigned u = __float_as_uint(f);
    return u ^ (((unsigned)((int)u >> 31)) | 0x80000000u);
}
__device__ __forceinline__ float key2f(unsigned k) {
    unsigned u = (k & 0x80000000u) ? (k ^ 0x80000000u) : ~k;
    return __uint_as_float(u);
}
__device__ __forceinline__ unsigned long long packki(unsigned k, int idx) {
    return ((unsigned long long)k << 32) | (unsigned)(2047 - idx);
}

// ---------------------------------------------------------------------------
// GEMM: sim = v1 @ v2^T, simT staged through smem.
// ---------------------------------------------------------------------------
__global__ __launch_bounds__(256, 2) void gemm_kernel(const float* __restrict__ v1,
                                                      const float* __restrict__ v2) {
    extern __shared__ float dsm[];
    float (*AsT)[128] = (float (*)[128])dsm;
    float (*BsT)[128] = (float (*)[128])(dsm + 64 * 128);

    const int t  = threadIdx.x;
    const int b  = blockIdx.z;
    const int q0 = blockIdx.y * 128;
    const int k0 = blockIdx.x * 128;

    {
        const int r  = t & 127;
        const int ds = (t >> 7) * 32;
        const float* a  = v1 + ((size_t)b * SEQ + q0 + r) * DIM + ds;
        const float* bp = v2 + ((size_t)b * SEQ + k0 + r) * DIM + ds;
#pragma unroll
        for (int i = 0; i < 8; i++) {
            float4 va = *(const float4*)(a + 4 * i);
            AsT[ds + 4 * i + 0][r] = va.x;
            AsT[ds + 4 * i + 1][r] = va.y;
            AsT[ds + 4 * i + 2][r] = va.z;
            AsT[ds + 4 * i + 3][r] = va.w;
            float4 vb = *(const float4*)(bp + 4 * i);
            BsT[ds + 4 * i + 0][r] = vb.x;
            BsT[ds + 4 * i + 1][r] = vb.y;
            BsT[ds + 4 * i + 2][r] = vb.z;
            BsT[ds + 4 * i + 3][r] = vb.w;
        }
    }
    __syncthreads();

    const int tx = t & 15;
    const int ty = t >> 4;

    float acc[8][8];
#pragma unroll
    for (int i = 0; i < 8; i++)
#pragma unroll
        for (int j = 0; j < 8; j++) acc[i][j] = 0.f;

#pragma unroll 8
    for (int d = 0; d < 64; d++) {
        float ar[8], br[8];
        *(float4*)&ar[0] = *(const float4*)&AsT[d][ty * 8];
        *(float4*)&ar[4] = *(const float4*)&AsT[d][ty * 8 + 4];
        *(float4*)&br[0] = *(const float4*)&BsT[d][tx * 8];
        *(float4*)&br[4] = *(const float4*)&BsT[d][tx * 8 + 4];
#pragma unroll
        for (int i = 0; i < 8; i++)
#pragma unroll
            for (int j = 0; j < 8; j++) acc[i][j] = fmaf(ar[i], br[j], acc[i][j]);
    }

    float* orow = g_sim + ((size_t)b * SEQ + q0 + ty * 8) * SEQ + k0 + tx * 8;
#pragma unroll
    for (int i = 0; i < 8; i++) {
        *(float4*)(orow + (size_t)i * SEQ)     = make_float4(acc[i][0], acc[i][1], acc[i][2], acc[i][3]);
        *(float4*)(orow + (size_t)i * SEQ + 4) = make_float4(acc[i][4], acc[i][5], acc[i][6], acc[i][7]);
    }

    float (*Ts)[129] = (float (*)[129])dsm;
#pragma unroll
    for (int kc = 0; kc < 4; kc++) {
        __syncthreads();
        if ((tx >> 2) == kc) {
            const int kl = (tx & 3) * 8;
            const int ql = ty * 8;
#pragma unroll
            for (int j = 0; j < 8; j++)
#pragma unroll
                for (int i = 0; i < 8; i++)
                    Ts[kl + j][ql + i] = acc[i][j];
        }
        __syncthreads();
#pragma unroll
        for (int e = t; e < 1024; e += 256) {
            const int rr = e >> 5;
            const int cc = (e & 31) * 4;
            float4 o;
            o.x = Ts[rr][cc];
            o.y = Ts[rr][cc + 1];
            o.z = Ts[rr][cc + 2];
            o.w = Ts[rr][cc + 3];
            *(float4*)(g_simT + ((size_t)b * SEQ + k0 + kc * 32 + rr) * SEQ + q0 + cc) = o;
        }
    }
}

// ---------------------------------------------------------------------------
// Block helpers (256 threads)
// ---------------------------------------------------------------------------
__device__ __forceinline__ unsigned suffix_excl_256(unsigned v, unsigned* ws) {
    __syncthreads();
    const int lane = threadIdx.x & 31;
    unsigned s = v;
#pragma unroll
    for (int o = 1; o < 32; o <<= 1) {
        unsigned n = __shfl_down_sync(0xffffffffu, s, o);
        if (lane + o < 32) s += n;
    }
    if (lane == 0) ws[threadIdx.x >> 5] = s;
    __syncthreads();
    unsigned cross = 0;
    const int w = threadIdx.x >> 5;
#pragma unroll
    for (int i = 0; i < 8; i++)
        if (i > w) cross += ws[i];
    return cross + (s - v);
}

__device__ __forceinline__ unsigned prefix_excl_256(unsigned v, unsigned* ws) {
    __syncthreads();
    const int lane = threadIdx.x & 31;
    unsigned s = v;
#pragma unroll
    for (int o = 1; o < 32; o <<= 1) {
        unsigned n = __shfl_up_sync(0xffffffffu, s, o);
        if (lane - o >= 0) s += n;
    }
    if (lane == 31) ws[threadIdx.x >> 5] = s;
    __syncthreads();
    unsigned cross = 0;
    const int w = threadIdx.x >> 5;
#pragma unroll
    for (int i = 0; i < 8; i++)
        if (i < w) cross += ws[i];
    return cross + (s - v);
}

__device__ __forceinline__ float block_max_256(float v, float* red) {
    __syncthreads();
#pragma unroll
    for (int o = 16; o > 0; o >>= 1) v = fmaxf(v, __shfl_xor_sync(0xffffffffu, v, o));
    if ((threadIdx.x & 31) == 0) red[threadIdx.x >> 5] = v;
    __syncthreads();
    return fmaxf(fmaxf(fmaxf(red[0], red[1]), fmaxf(red[2], red[3])),
                 fmaxf(fmaxf(red[4], red[5]), fmaxf(red[6], red[7])));
}

__device__ __forceinline__ float block_sum_256(float v, float* red) {
    __syncthreads();
#pragma unroll
    for (int o = 16; o > 0; o >>= 1) v += __shfl_xor_sync(0xffffffffu, v, o);
    if ((threadIdx.x & 31) == 0) red[threadIdx.x >> 5] = v;
    __syncthreads();
    return ((red[0] + red[1]) + (red[2] + red[3])) + ((red[4] + red[5]) + (red[6] + red[7]));
}

// ---------------------------------------------------------------------------
// Row top-k softmax reduce. One block (256 thr) per (b, row, direction).
// All float4-accessed members 16B-aligned (misaligned-address fix from R4).
// ---------------------------------------------------------------------------
struct RSmem {
    unsigned long long list[SEQ];   // 16 KB, offset 0 (16B aligned)
    unsigned           hist[2048];  // 8 KB
    alignas(16) float  wacc[8][64]; // 2 KB, float4 accessed -> 16B aligned
    alignas(16) float  sel_w[KTOP];
    int      sel_idx[KTOP];
    unsigned long long memb[64];
    unsigned long long Tp;
    unsigned ws[8];
    float    red[8];
    int      c_cnt, m_cnt, bb, wrem_s;
};

__global__ __launch_bounds__(256, 5) void topk_reduce_kernel(
    const float* __restrict__ simp, const float* __restrict__ simtp,
    const float* __restrict__ v1,  const float* __restrict__ v2,
    const unsigned char* __restrict__ v1m, const unsigned char* __restrict__ v2m,
    float* __restrict__ out1, float* __restrict__ out2) {
    __shared__ RSmem sm;
    const int t = threadIdx.x;
    const int r = blockIdx.x;
    const int b = blockIdx.y;
    const int z = blockIdx.z;

    const float* simbase      = z ? simtp : simp;
    const float* V            = z ? v1    : v2;
    const unsigned char* km   = z ? v1m   : v2m;
    const unsigned char* rmsk = z ? v2m   : v1m;
    float* out                = z ? out2  : out1;

    const float* srow = simbase + ((size_t)b * SEQ + r) * SEQ;
    const unsigned char* kmb = km + (size_t)b * SEQ;
    const int base = t * 8;

    // ---- load masked scores (8 contiguous per thread, streaming)
    float vs[8];
    {
        float4 a0 = __ldcs((const float4*)(srow + base));
        float4 a1 = __ldcs((const float4*)(srow + base + 4));
        vs[0] = a0.x; vs[1] = a0.y; vs[2] = a0.z; vs[3] = a0.w;
        vs[4] = a1.x; vs[5] = a1.y; vs[6] = a1.z; vs[7] = a1.w;
#pragma unroll
        for (int j = 0; j < 8; j++)
            if (kmb[base + j]) vs[j] = -FLT_MAX;
    }
    float lm = vs[0];
#pragma unroll
    for (int j = 1; j < 8; j++) lm = fmaxf(lm, vs[j]);
    const float m = block_max_256(lm, sm.red);

    // ---- candidate compaction: key >= f2key(m-20) (warp-aggregated append)
    unsigned kmin = f2key(m - 20.0f);
    const int lane = t & 31;
    const unsigned lmask = (1u << lane) - 1u;
    if (t == 0) sm.c_cnt = 0;
    __syncthreads();
#pragma unroll
    for (int j = 0; j < 8; j++) {
        unsigned k = f2key(vs[j]);
        bool cand = (k >= kmin);
        unsigned bal = __ballot_sync(0xffffffffu, cand);
        int wbase = 0;
        if (lane == 0 && bal) wbase = atomicAdd(&sm.c_cnt, __popc(bal));
        wbase = __shfl_sync(0xffffffffu, wbase, 0);
        if (cand) sm.list[wbase + __popc(bal & lmask)] = packki(k, base + j);
    }
    __syncthreads();
    int c = sm.c_cnt;
    if (c < KTOP) {  // rare fallback: take everything (exact)
        __syncthreads();
        if (t == 0) sm.c_cnt = 0;
        __syncthreads();
#pragma unroll
        for (int j = 0; j < 8; j++) {
            unsigned k = f2key(vs[j]);
            unsigned bal = __ballot_sync(0xffffffffu, true);
            int wbase = 0;
            if (lane == 0) wbase = atomicAdd(&sm.c_cnt, 32);
            wbase = __shfl_sync(0xffffffffu, wbase, 0);
            sm.list[wbase + __popc(bal & lmask)] = packki(k, base + j);
        }
        __syncthreads();
        c = SEQ;
        kmin = 0;
    }

    // ---- denom over candidates only
    float ld = 0.f;
    for (int i = t; i < c; i += 256)
        ld += __expf(key2f((unsigned)(sm.list[i] >> 32)) - m);
    const float denom = block_sum_256(ld, sm.red);

    // ---- dynamic-range radix select of the KTOP-th largest packed rank key
    unsigned kmax = f2key(m);
    unsigned W = kmax - kmin;
    int s = 0;
    while ((W >> s) >= 2048u) s++;
    unsigned lo = kmin;
    int nbins = 2048;
    int wrem = KTOP;
    unsigned long long T = 0;
    bool done = false;

    for (int round = 0; round < 6 && !done; round++) {
        for (int i = t; i < 2048; i += 256) sm.hist[i] = 0u;
        __syncthreads();
        for (int i = t; i < c; i += 256) {
            unsigned k = (unsigned)(sm.list[i] >> 32);
            if (k >= lo) {
                unsigned bin = (k - lo) >> s;
                if (bin < (unsigned)nbins) atomicAdd(&sm.hist[bin], 1u);
            }
        }
        __syncthreads();
        unsigned cnt8[8], tot = 0;
#pragma unroll
        for (int j = 0; j < 8; j++) { cnt8[j] = sm.hist[t * 8 + j]; tot += cnt8[j]; }
        unsigned se = suffix_excl_256(tot, sm.ws);
        unsigned cum = se;
#pragma unroll
        for (int j = 7; j >= 0; j--) {
            unsigned ci = cum + cnt8[j];
            if (cum < (unsigned)wrem && ci >= (unsigned)wrem) {
                sm.bb     = t * 8 + j;
                sm.wrem_s = wrem - (int)cum;
            }
            cum = ci;
        }
        __syncthreads();
        lo   = lo + ((unsigned)sm.bb << s);
        wrem = sm.wrem_s;
        __syncthreads();

        if (s == 0) {
            // key fully resolved; break ties on the 11 packed index bits
            for (int i = t; i < 2048; i += 256) sm.hist[i] = 0u;
            __syncthreads();
            for (int i = t; i < c; i += 256) {
                unsigned long long p = sm.list[i];
                if ((unsigned)(p >> 32) == lo)
                    atomicAdd(&sm.hist[(unsigned)p & 2047u], 1u);
            }
            __syncthreads();
            unsigned c8[8], tt = 0;
#pragma unroll
            for (int j = 0; j < 8; j++) { c8[j] = sm.hist[t * 8 + j]; tt += c8[j]; }
            unsigned se2 = suffix_excl_256(tt, sm.ws);
            unsigned cm = se2;
#pragma unroll
            for (int j = 7; j >= 0; j--) {
                unsigned ci = cm + c8[j];
                if (cm < (unsigned)wrem && ci >= (unsigned)wrem)
                    sm.Tp = ((unsigned long long)lo << 32) | (unsigned)(t * 8 + j);
                cm = ci;
            }
            __syncthreads();
            T = sm.Tp;
            done = true;
        } else {
            // collect boundary-bin members (usually 1-3)
            if (t == 0) sm.m_cnt = 0;
            __syncthreads();
            for (int i = t; i < c; i += 256) {
                unsigned k = (unsigned)(sm.list[i] >> 32);
                if (k >= lo && ((k - lo) >> s) == 0u) {
                    int p = atomicAdd(&sm.m_cnt, 1);
                    if (p < 64) sm.memb[p] = sm.list[i];
                }
            }
            __syncthreads();
            int mc = sm.m_cnt;
            if (mc <= 64) {
                if (t < 32) {
                    for (int i = lane; i < mc; i += 32) {
                        unsigned long long v = sm.memb[i];
                        int rank = 0;
                        for (int j = 0; j < mc; j++) rank += (sm.memb[j] > v);
                        if (rank == wrem - 1) sm.Tp = v;
                    }
                }
                __syncthreads();
                T = sm.Tp;
                done = true;
            } else {
                int snew = (s > 11) ? (s - 11) : 0;
                nbins = 1 << (s - snew);
                s = snew;
            }
        }
    }

    // ---- selection: packed >= T gives exactly KTOP entries (distinct keys)
    unsigned flags = 0;
    int lcnt = 0;
#pragma unroll
    for (int j = 0; j < 8; j++) {
        if (packki(f2key(vs[j]), base + j) >= T) { flags |= (1u << j); lcnt++; }
    }
    unsigned pe = prefix_excl_256((unsigned)lcnt, sm.ws);
    {
        int pos = (int)pe;
#pragma unroll
        for (int j = 0; j < 8; j++)
            if (flags & (1u << j)) {
                if (pos < KTOP) {
                    sm.sel_idx[pos] = base + j;
                    sm.sel_w[pos]   = __expf(vs[j] - m);
                }
                pos++;
            }
    }
    __syncthreads();

    // ---- gather: half-warp per selected row, independent float4 loads
    const float* Vb = V + (size_t)b * SEQ * DIM;
    const int w    = t >> 5;
    const int half = lane >> 4;
    const int li   = lane & 15;
    float4 acc = make_float4(0.f, 0.f, 0.f, 0.f);
#pragma unroll
    for (int it = 0; it < 8; it++) {
        const int j = it * 16 + w * 2 + half;
        const int   idx = sm.sel_idx[j];
        const float wgt = sm.sel_w[j];
        const float4 val = __ldg((const float4*)(Vb + (size_t)idx * DIM + li * 4));
        acc.x = fmaf(wgt, val.x, acc.x);
        acc.y = fmaf(wgt, val.y, acc.y);
        acc.z = fmaf(wgt, val.z, acc.z);
        acc.w = fmaf(wgt, val.w, acc.w);
    }
    acc.x += __shfl_xor_sync(0xffffffffu, acc.x, 16);
    acc.y += __shfl_xor_sync(0xffffffffu, acc.y, 16);
    acc.z += __shfl_xor_sync(0xffffffffu, acc.z, 16);
    acc.w += __shfl_xor_sync(0xffffffffu, acc.w, 16);
    if (half == 0) *(float4*)&sm.wacc[w][li * 4] = acc;
    __syncthreads();
    if (t < 64) {
        float sacc = 0.f;
#pragma unroll
        for (int ww = 0; ww < 8; ww++) sacc += sm.wacc[ww][t];
        const bool rmk = rmsk[(size_t)b * SEQ + r] != 0;
        out[((size_t)b * SEQ + r) * DIM + t] = rmk ? 0.f : sacc * (1.f / denom);
    }
}

// ---------------------------------------------------------------------------
// Launch
// ---------------------------------------------------------------------------
extern "C" void kernel_launch(void* const* d_in, const int* in_sizes, int n_in,
                              void* d_out, int out_size) {
    const float*         v1  = (const float*)d_in[0];
    const unsigned char* v1m = (const unsigned char*)d_in[1];
    const float*         v2  = (const float*)d_in[2];
    const unsigned char* v2m = (const unsigned char*)d_in[3];
    float* out1 = (float*)d_out;
    float* out2 = out1 + (size_t)BATCH * SEQ * DIM;

    float* simp;  cudaGetSymbolAddress((void**)&simp,  g_sim);
    float* simtp; cudaGetSymbolAddress((void**)&simtp, g_simT);

    const int gemm_smem = 2 * 64 * 128 * (int)sizeof(float);  // 64 KB
    cudaFuncSetAttribute((const void*)gemm_kernel,
                         cudaFuncAttributeMaxDynamicSharedMemorySize, gemm_smem);

    dim3 gg(SEQ / 128, SEQ / 128, BATCH);
    gemm_kernel<<<gg, 256, gemm_smem>>>(v1, v2);

    dim3 gr(SEQ, BATCH, 2);
    topk_reduce_kernel<<<gr, 256>>>(simp, simtp, v1, v2, v1m, v2m, out1, out2);
}

// round 6
// speedup vs baseline: 1.0960x; 1.0960x over previous
#include <cuda_runtime.h>
#include <cuda_bf16.h>
#include <cfloat>
#include <cstdint>
#include <cstddef>

#define BATCH 16
#define SEQ   2048
#define DIM   64
#define KTOP  128

// 268 MB each: sim[b][q][k] and its transpose simT[b][k][q]
__device__ float g_sim [(size_t)BATCH * SEQ * SEQ];
__device__ float g_simT[(size_t)BATCH * SEQ * SEQ];

// Order-preserving float <-> uint key (larger float => larger key)
__device__ __forceinline__ unsigned f2key(float f) {
    unsigned u = __float_as_uint(f);
    return u ^ (((unsigned)((int)u >> 31)) | 0x80000000u);
}
__device__ __forceinline__ float key2f(unsigned k) {
    unsigned u = (k & 0x80000000u) ? (k ^ 0x80000000u) : ~k;
    return __uint_as_float(u);
}

// ---------------------------------------------------------------------------
// GEMM: sim = v1 @ v2^T, simT staged through smem. (validated in R3/R5)
// ---------------------------------------------------------------------------
__global__ __launch_bounds__(256, 2) void gemm_kernel(const float* __restrict__ v1,
                                                      const float* __restrict__ v2) {
    extern __shared__ float dsm[];
    float (*AsT)[128] = (float (*)[128])dsm;
    float (*BsT)[128] = (float (*)[128])(dsm + 64 * 128);

    const int t  = threadIdx.x;
    const int b  = blockIdx.z;
    const int q0 = blockIdx.y * 128;
    const int k0 = blockIdx.x * 128;

    {
        const int r  = t & 127;
        const int ds = (t >> 7) * 32;
        const float* a  = v1 + ((size_t)b * SEQ + q0 + r) * DIM + ds;
        const float* bp = v2 + ((size_t)b * SEQ + k0 + r) * DIM + ds;
#pragma unroll
        for (int i = 0; i < 8; i++) {
            float4 va = *(const float4*)(a + 4 * i);
            AsT[ds + 4 * i + 0][r] = va.x;
            AsT[ds + 4 * i + 1][r] = va.y;
            AsT[ds + 4 * i + 2][r] = va.z;
            AsT[ds + 4 * i + 3][r] = va.w;
            float4 vb = *(const float4*)(bp + 4 * i);
            BsT[ds + 4 * i + 0][r] = vb.x;
            BsT[ds + 4 * i + 1][r] = vb.y;
            BsT[ds + 4 * i + 2][r] = vb.z;
            BsT[ds + 4 * i + 3][r] = vb.w;
        }
    }
    __syncthreads();

    const int tx = t & 15;
    const int ty = t >> 4;

    float acc[8][8];
#pragma unroll
    for (int i = 0; i < 8; i++)
#pragma unroll
        for (int j = 0; j < 8; j++) acc[i][j] = 0.f;

#pragma unroll 8
    for (int d = 0; d < 64; d++) {
        float ar[8], br[8];
        *(float4*)&ar[0] = *(const float4*)&AsT[d][ty * 8];
        *(float4*)&ar[4] = *(const float4*)&AsT[d][ty * 8 + 4];
        *(float4*)&br[0] = *(const float4*)&BsT[d][tx * 8];
        *(float4*)&br[4] = *(const float4*)&BsT[d][tx * 8 + 4];
#pragma unroll
        for (int i = 0; i < 8; i++)
#pragma unroll
            for (int j = 0; j < 8; j++) acc[i][j] = fmaf(ar[i], br[j], acc[i][j]);
    }

    float* orow = g_sim + ((size_t)b * SEQ + q0 + ty * 8) * SEQ + k0 + tx * 8;
#pragma unroll
    for (int i = 0; i < 8; i++) {
        *(float4*)(orow + (size_t)i * SEQ)     = make_float4(acc[i][0], acc[i][1], acc[i][2], acc[i][3]);
        *(float4*)(orow + (size_t)i * SEQ + 4) = make_float4(acc[i][4], acc[i][5], acc[i][6], acc[i][7]);
    }

    float (*Ts)[129] = (float (*)[129])dsm;
#pragma unroll
    for (int kc = 0; kc < 4; kc++) {
        __syncthreads();
        if ((tx >> 2) == kc) {
            const int kl = (tx & 3) * 8;
            const int ql = ty * 8;
#pragma unroll
            for (int j = 0; j < 8; j++)
#pragma unroll
                for (int i = 0; i < 8; i++)
                    Ts[kl + j][ql + i] = acc[i][j];
        }
        __syncthreads();
#pragma unroll
        for (int e = t; e < 1024; e += 256) {
            const int rr = e >> 5;
            const int cc = (e & 31) * 4;
            float4 o;
            o.x = Ts[rr][cc];
            o.y = Ts[rr][cc + 1];
            o.z = Ts[rr][cc + 2];
            o.w = Ts[rr][cc + 3];
            *(float4*)(g_simT + ((size_t)b * SEQ + k0 + kc * 32 + rr) * SEQ + q0 + cc) = o;
        }
    }
}

// ---------------------------------------------------------------------------
// Block helpers (256 threads)
// ---------------------------------------------------------------------------
__device__ __forceinline__ unsigned suffix_excl_256(unsigned v, unsigned* ws) {
    __syncthreads();
    const int lane = threadIdx.x & 31;
    unsigned s = v;
#pragma unroll
    for (int o = 1; o < 32; o <<= 1) {
        unsigned n = __shfl_down_sync(0xffffffffu, s, o);
        if (lane + o < 32) s += n;
    }
    if (lane == 0) ws[threadIdx.x >> 5] = s;
    __syncthreads();
    unsigned cross = 0;
    const int w = threadIdx.x >> 5;
#pragma unroll
    for (int i = 0; i < 8; i++)
        if (i > w) cross += ws[i];
    return cross + (s - v);
}

__device__ __forceinline__ unsigned prefix_excl_256(unsigned v, unsigned* ws) {
    __syncthreads();
    const int lane = threadIdx.x & 31;
    unsigned s = v;
#pragma unroll
    for (int o = 1; o < 32; o <<= 1) {
        unsigned n = __shfl_up_sync(0xffffffffu, s, o);
        if (lane - o >= 0) s += n;
    }
    if (lane == 31) ws[threadIdx.x >> 5] = s;
    __syncthreads();
    unsigned cross = 0;
    const int w = threadIdx.x >> 5;
#pragma unroll
    for (int i = 0; i < 8; i++)
        if (i < w) cross += ws[i];
    return cross + (s - v);
}

__device__ __forceinline__ float block_max_256(float v, float* red) {
    __syncthreads();
#pragma unroll
    for (int o = 16; o > 0; o >>= 1) v = fmaxf(v, __shfl_xor_sync(0xffffffffu, v, o));
    if ((threadIdx.x & 31) == 0) red[threadIdx.x >> 5] = v;
    __syncthreads();
    return fmaxf(fmaxf(fmaxf(red[0], red[1]), fmaxf(red[2], red[3])),
                 fmaxf(fmaxf(red[4], red[5]), fmaxf(red[6], red[7])));
}

__device__ __forceinline__ float block_sum_256(float v, float* red) {
    __syncthreads();
#pragma unroll
    for (int o = 16; o > 0; o >>= 1) v += __shfl_xor_sync(0xffffffffu, v, o);
    if ((threadIdx.x & 31) == 0) red[threadIdx.x >> 5] = v;
    __syncthreads();
    return ((red[0] + red[1]) + (red[2] + red[3])) + ((red[4] + red[5]) + (red[6] + red[7]));
}

// ---------------------------------------------------------------------------
// Row top-k softmax reduce (instruction-lean). One block per (b, row, dir).
// 32-bit keys; 256-bin dynamic-range radix; ties by index order (jax rule).
// ---------------------------------------------------------------------------
struct RSmem {
    alignas(16) float wacc[8][64];   // float4 accessed -> 16B aligned
    int2     sel[KTOP];              // (idx, weight bits)
    unsigned list[SEQ];              // candidate keys (32-bit)
    unsigned hist[256];
    unsigned memb[256];
    unsigned ws[8];
    float    red[8];
    unsigned Tkey;
    int      c_cnt, m_cnt, bb, wrem_s, ntot;
};

__global__ __launch_bounds__(256) void topk_reduce_kernel(
    const float* __restrict__ simp, const float* __restrict__ simtp,
    const float* __restrict__ v1,  const float* __restrict__ v2,
    const unsigned char* __restrict__ v1m, const unsigned char* __restrict__ v2m,
    float* __restrict__ out1, float* __restrict__ out2) {
    __shared__ RSmem sm;
    const int t = threadIdx.x;
    const int r = blockIdx.x;
    const int b = blockIdx.y;
    const int z = blockIdx.z;

    const float* simbase      = z ? simtp : simp;
    const float* V            = z ? v1    : v2;
    const unsigned char* km   = z ? v1m   : v2m;
    const unsigned char* rmsk = z ? v2m   : v1m;
    float* out                = z ? out2  : out1;

    const float* srow = simbase + ((size_t)b * SEQ + r) * SEQ;
    const unsigned char* kmb = km + (size_t)b * SEQ;
    const int base = t * 8;
    const int lane = t & 31;
    const unsigned lmask = (1u << lane) - 1u;

    // ---- load masked scores (8 contiguous per thread, streaming)
    float vs[8];
    {
        float4 a0 = __ldcs((const float4*)(srow + base));
        float4 a1 = __ldcs((const float4*)(srow + base + 4));
        unsigned long long mk = *(const unsigned long long*)(kmb + base);
        vs[0] = a0.x; vs[1] = a0.y; vs[2] = a0.z; vs[3] = a0.w;
        vs[4] = a1.x; vs[5] = a1.y; vs[6] = a1.z; vs[7] = a1.w;
#pragma unroll
        for (int j = 0; j < 8; j++)
            if ((mk >> (8 * j)) & 0xffull) vs[j] = -FLT_MAX;
    }
    float lm = vs[0];
#pragma unroll
    for (int j = 1; j < 8; j++) lm = fmaxf(lm, vs[j]);
    const float m = block_max_256(lm, sm.red);

    // ---- radix params (known immediately from m)
    unsigned kmin = f2key(m - 20.0f);      // excluded tail: < 2048*e^-20 rel denom error
    unsigned W    = f2key(m) - kmin;
    int s;
    { int bits = 32 - __clz(W | 1u); s = bits > 8 ? bits - 8 : 0; }

    sm.hist[t] = 0u;
    if (t == 0) sm.c_cnt = 0;
    __syncthreads();

    // ---- candidate compaction + fused 256-bin histogram
#pragma unroll
    for (int j = 0; j < 8; j++) {
        unsigned k = f2key(vs[j]);
        bool cand = (k >= kmin);
        unsigned bal = __ballot_sync(0xffffffffu, cand);
        int wbase = 0;
        if (lane == 0 && bal) wbase = atomicAdd(&sm.c_cnt, __popc(bal));
        wbase = __shfl_sync(0xffffffffu, wbase, 0);
        if (cand) {
            sm.list[wbase + __popc(bal & lmask)] = k;
            atomicAdd(&sm.hist[(k - kmin) >> s], 1u);
        }
    }
    __syncthreads();
    int c = sm.c_cnt;
    if (c < KTOP) {            // rare exact fallback: take all 2048
        __syncthreads();
        sm.hist[t] = 0u;
        if (t == 0) sm.c_cnt = 0;
        __syncthreads();
        kmin = 0u; s = 24;
#pragma unroll
        for (int j = 0; j < 8; j++) {
            unsigned k = f2key(vs[j]);
            unsigned bal = __ballot_sync(0xffffffffu, true);
            int wbase = 0;
            if (lane == 0) wbase = atomicAdd(&sm.c_cnt, 32);
            wbase = __shfl_sync(0xffffffffu, wbase, 0);
            sm.list[wbase + __popc(bal & lmask)] = k;
            atomicAdd(&sm.hist[k >> 24], 1u);
        }
        __syncthreads();
        c = SEQ;
    }

    // ---- denom over candidates only (dense MUFU loop, ~2 iters)
    float ld = 0.f;
    for (int i = t; i < c; i += 256)
        ld += __expf(key2f(sm.list[i]) - m);
    const float denom = block_sum_256(ld, sm.red);

    // ---- dynamic-range radix select: exact key T of the KTOP-th largest
    unsigned lo = kmin;
    int wrem = KTOP;
    unsigned T;
    while (true) {
        unsigned v  = sm.hist[t];
        unsigned se = suffix_excl_256(v, sm.ws);
        if (se < (unsigned)wrem && se + v >= (unsigned)wrem) {
            sm.bb     = t;
            sm.wrem_s = wrem - (int)se;
        }
        __syncthreads();
        lo  += ((unsigned)sm.bb) << s;
        wrem = sm.wrem_s;
        if (s == 0) { T = lo; break; }

        // collect boundary-window members (expected ~2)
        if (t == 0) sm.m_cnt = 0;
        __syncthreads();
        for (int i = t; i < c; i += 256) {
            unsigned k = sm.list[i];
            if (k >= lo && ((k - lo) >> s) == 0u) {
                int p = atomicAdd(&sm.m_cnt, 1);
                if (p < 256) sm.memb[p] = k;
            }
        }
        __syncthreads();
        const int mc = sm.m_cnt;
        if (mc <= 64) {
            if (t < 32) {
                for (int i = t; i < mc; i += 32) {
                    unsigned vv = sm.memb[i];
                    int rk = 0, eq = 0;
                    for (int j2 = 0; j2 < mc; j2++) {
                        rk += (sm.memb[j2] > vv);
                        eq += (sm.memb[j2] == vv);
                    }
                    if (rk < wrem && wrem <= rk + eq) sm.Tkey = vv;
                }
            }
            __syncthreads();
            T = sm.Tkey;
            break;
        }
        // rare: refine window with finer bins over the candidate list
        {
            int snew = s > 8 ? s - 8 : 0;
            sm.hist[t] = 0u;
            __syncthreads();
            for (int i = t; i < c; i += 256) {
                unsigned k = sm.list[i];
                if (k >= lo && ((k - lo) >> s) == 0u)
                    atomicAdd(&sm.hist[(k - lo) >> snew], 1u);
            }
            s = snew;
            __syncthreads();
        }
    }

    // ---- selection: all keys > T, then keys == T in index order (jax tie rule)
    unsigned fgt = 0, feq = 0;
    int lgt = 0, leq = 0;
#pragma unroll
    for (int j = 0; j < 8; j++) {
        unsigned k = f2key(vs[j]);
        if (k > T)       { fgt |= (1u << j); lgt++; }
        else if (k == T) { feq |= (1u << j); leq++; }
    }
    unsigned packed = ((unsigned)lgt << 16) | (unsigned)leq;
    unsigned pe = prefix_excl_256(packed, sm.ws);
    if (t == 255) sm.ntot = (int)(pe + packed);
    __syncthreads();
    const int ngtot = sm.ntot >> 16;
    const int n = min(KTOP, ngtot + (sm.ntot & 0xffff));
    {
        int pos = (int)(pe >> 16);
#pragma unroll
        for (int j = 0; j < 8; j++)
            if (fgt & (1u << j)) {
                sm.sel[pos] = make_int2(base + j, __float_as_int(__expf(vs[j] - m)));
                pos++;
            }
        pos = ngtot + (int)(pe & 0xffff);
#pragma unroll
        for (int j = 0; j < 8; j++)
            if (feq & (1u << j)) {
                if (pos < KTOP)
                    sm.sel[pos] = make_int2(base + j, __float_as_int(__expf(vs[j] - m)));
                pos++;
            }
    }
    __syncthreads();

    // ---- gather: half-warp per selected row, independent float4 loads
    const float* Vb = V + (size_t)b * SEQ * DIM;
    const int w    = t >> 5;
    const int half = lane >> 4;
    const int li   = lane & 15;
    float4 acc = make_float4(0.f, 0.f, 0.f, 0.f);
#pragma unroll
    for (int it = 0; it < 8; it++) {
        const int j = it * 16 + w * 2 + half;
        if (j < n) {
            const int2  se2 = sm.sel[j];
            const float wgt = __int_as_float(se2.y);
            const float4 val = __ldg((const float4*)(Vb + (size_t)se2.x * DIM + li * 4));
            acc.x = fmaf(wgt, val.x, acc.x);
            acc.y = fmaf(wgt, val.y, acc.y);
            acc.z = fmaf(wgt, val.z, acc.z);
            acc.w = fmaf(wgt, val.w, acc.w);
        }
    }
    acc.x += __shfl_xor_sync(0xffffffffu, acc.x, 16);
    acc.y += __shfl_xor_sync(0xffffffffu, acc.y, 16);
    acc.z += __shfl_xor_sync(0xffffffffu, acc.z, 16);
    acc.w += __shfl_xor_sync(0xffffffffu, acc.w, 16);
    if (half == 0) *(float4*)&sm.wacc[w][li * 4] = acc;
    __syncthreads();
    if (t < 64) {
        float sacc = 0.f;
#pragma unroll
        for (int ww = 0; ww < 8; ww++) sacc += sm.wacc[ww][t];
        const bool rmk = rmsk[(size_t)b * SEQ + r] != 0;
        out[((size_t)b * SEQ + r) * DIM + t] = rmk ? 0.f : sacc * (1.f / denom);
    }
}

// ---------------------------------------------------------------------------
// Launch
// ---------------------------------------------------------------------------
extern "C" void kernel_launch(void* const* d_in, const int* in_sizes, int n_in,
                              void* d_out, int out_size) {
    const float*         v1  = (const float*)d_in[0];
    const unsigned char* v1m = (const unsigned char*)d_in[1];
    const float*         v2  = (const float*)d_in[2];
    const unsigned char* v2m = (const unsigned char*)d_in[3];
    float* out1 = (float*)d_out;
    float* out2 = out1 + (size_t)BATCH * SEQ * DIM;

    float* simp;  cudaGetSymbolAddress((void**)&simp,  g_sim);
    float* simtp; cudaGetSymbolAddress((void**)&simtp, g_simT);

    const int gemm_smem = 2 * 64 * 128 * (int)sizeof(float);  // 64 KB
    cudaFuncSetAttribute((const void*)gemm_kernel,
                         cudaFuncAttributeMaxDynamicSharedMemorySize, gemm_smem);

    dim3 gg(SEQ / 128, SEQ / 128, BATCH);
    gemm_kernel<<<gg, 256, gemm_smem>>>(v1, v2);

    dim3 gr(SEQ, BATCH, 2);
    topk_reduce_kernel<<<gr, 256>>>(simp, simtp, v1, v2, v1m, v2m, out1, out2);
}

// round 7
// speedup vs baseline: 1.1921x; 1.0877x over previous
#include <cuda_runtime.h>
#include <cuda_bf16.h>
#include <cfloat>
#include <cstdint>
#include <cstddef>

#define BATCH 16
#define SEQ   2048
#define DIM   64
#define KTOP  128

// 268 MB each: sim[b][q][k] and its transpose simT[b][k][q]
__device__ float g_sim [(size_t)BATCH * SEQ * SEQ];
__device__ float g_simT[(size_t)BATCH * SEQ * SEQ];

// Order-preserving float <-> uint key (larger float => larger key)
__device__ __forceinline__ unsigned f2key(float f) {
    unsigned u = __float_as_uint(f);
    return u ^ (((unsigned)((int)u >> 31)) | 0x80000000u);
}
__device__ __forceinline__ float key2f(unsigned k) {
    unsigned u = (k & 0x80000000u) ? (k ^ 0x80000000u) : ~k;
    return __uint_as_float(u);
}

// ---------------------------------------------------------------------------
// GEMM: sim = v1 @ v2^T ; simT written directly from registers (R2 variant,
// measured faster than smem staging).
// ---------------------------------------------------------------------------
__global__ __launch_bounds__(256, 2) void gemm_kernel(const float* __restrict__ v1,
                                                      const float* __restrict__ v2) {
    extern __shared__ float dsm[];
    float (*AsT)[128] = (float (*)[128])dsm;
    float (*BsT)[128] = (float (*)[128])(dsm + 64 * 128);

    const int t  = threadIdx.x;
    const int b  = blockIdx.z;
    const int q0 = blockIdx.y * 128;
    const int k0 = blockIdx.x * 128;

    {
        const int r  = t & 127;
        const int ds = (t >> 7) * 32;
        const float* a  = v1 + ((size_t)b * SEQ + q0 + r) * DIM + ds;
        const float* bp = v2 + ((size_t)b * SEQ + k0 + r) * DIM + ds;
#pragma unroll
        for (int i = 0; i < 8; i++) {
            float4 va = *(const float4*)(a + 4 * i);
            AsT[ds + 4 * i + 0][r] = va.x;
            AsT[ds + 4 * i + 1][r] = va.y;
            AsT[ds + 4 * i + 2][r] = va.z;
            AsT[ds + 4 * i + 3][r] = va.w;
            float4 vb = *(const float4*)(bp + 4 * i);
            BsT[ds + 4 * i + 0][r] = vb.x;
            BsT[ds + 4 * i + 1][r] = vb.y;
            BsT[ds + 4 * i + 2][r] = vb.z;
            BsT[ds + 4 * i + 3][r] = vb.w;
        }
    }
    __syncthreads();

    const int tx = t & 15;
    const int ty = t >> 4;

    float acc[8][8];
#pragma unroll
    for (int i = 0; i < 8; i++)
#pragma unroll
        for (int j = 0; j < 8; j++) acc[i][j] = 0.f;

#pragma unroll 8
    for (int d = 0; d < 64; d++) {
        float ar[8], br[8];
        *(float4*)&ar[0] = *(const float4*)&AsT[d][ty * 8];
        *(float4*)&ar[4] = *(const float4*)&AsT[d][ty * 8 + 4];
        *(float4*)&br[0] = *(const float4*)&BsT[d][tx * 8];
        *(float4*)&br[4] = *(const float4*)&BsT[d][tx * 8 + 4];
#pragma unroll
        for (int i = 0; i < 8; i++)
#pragma unroll
            for (int j = 0; j < 8; j++) acc[i][j] = fmaf(ar[i], br[j], acc[i][j]);
    }

    float* orow = g_sim + ((size_t)b * SEQ + q0 + ty * 8) * SEQ + k0 + tx * 8;
#pragma unroll
    for (int i = 0; i < 8; i++) {
        *(float4*)(orow + (size_t)i * SEQ)     = make_float4(acc[i][0], acc[i][1], acc[i][2], acc[i][3]);
        *(float4*)(orow + (size_t)i * SEQ + 4) = make_float4(acc[i][4], acc[i][5], acc[i][6], acc[i][7]);
    }
    float* trow = g_simT + ((size_t)b * SEQ + k0 + tx * 8) * SEQ + q0 + ty * 8;
#pragma unroll
    for (int j = 0; j < 8; j++) {
        *(float4*)(trow + (size_t)j * SEQ)     = make_float4(acc[0][j], acc[1][j], acc[2][j], acc[3][j]);
        *(float4*)(trow + (size_t)j * SEQ + 4) = make_float4(acc[4][j], acc[5][j], acc[6][j], acc[7][j]);
    }
}

// ---------------------------------------------------------------------------
// Block helpers (256 threads)
// ---------------------------------------------------------------------------
__device__ __forceinline__ unsigned suffix_excl_256(unsigned v, unsigned* ws) {
    __syncthreads();
    const int lane = threadIdx.x & 31;
    unsigned s = v;
#pragma unroll
    for (int o = 1; o < 32; o <<= 1) {
        unsigned n = __shfl_down_sync(0xffffffffu, s, o);
        if (lane + o < 32) s += n;
    }
    if (lane == 0) ws[threadIdx.x >> 5] = s;
    __syncthreads();
    unsigned cross = 0;
    const int w = threadIdx.x >> 5;
#pragma unroll
    for (int i = 0; i < 8; i++)
        if (i > w) cross += ws[i];
    return cross + (s - v);
}

__device__ __forceinline__ unsigned prefix_excl_256(unsigned v, unsigned* ws) {
    __syncthreads();
    const int lane = threadIdx.x & 31;
    unsigned s = v;
#pragma unroll
    for (int o = 1; o < 32; o <<= 1) {
        unsigned n = __shfl_up_sync(0xffffffffu, s, o);
        if (lane - o >= 0) s += n;
    }
    if (lane == 31) ws[threadIdx.x >> 5] = s;
    __syncthreads();
    unsigned cross = 0;
    const int w = threadIdx.x >> 5;
#pragma unroll
    for (int i = 0; i < 8; i++)
        if (i < w) cross += ws[i];
    return cross + (s - v);
}

__device__ __forceinline__ float block_max_256(float v, float* red) {
    __syncthreads();
#pragma unroll
    for (int o = 16; o > 0; o >>= 1) v = fmaxf(v, __shfl_xor_sync(0xffffffffu, v, o));
    if ((threadIdx.x & 31) == 0) red[threadIdx.x >> 5] = v;
    __syncthreads();
    return fmaxf(fmaxf(fmaxf(red[0], red[1]), fmaxf(red[2], red[3])),
                 fmaxf(fmaxf(red[4], red[5]), fmaxf(red[6], red[7])));
}

__device__ __forceinline__ float block_sum_256(float v, float* red) {
    __syncthreads();
#pragma unroll
    for (int o = 16; o > 0; o >>= 1) v += __shfl_xor_sync(0xffffffffu, v, o);
    if ((threadIdx.x & 31) == 0) red[threadIdx.x >> 5] = v;
    __syncthreads();
    return ((red[0] + red[1]) + (red[2] + red[3])) + ((red[4] + red[5]) + (red[6] + red[7]));
}

// ---------------------------------------------------------------------------
// Row top-k softmax reduce. One block per (b, row, dir).
// Single sweep over 2048; everything else on the index-ordered candidate list.
// ---------------------------------------------------------------------------
struct RSmem {
    alignas(16) float wacc[8][64];   // float4 accessed -> 16B aligned
    alignas(16) int2  sel[KTOP];     // (idx, weight bits), index-ordered
    int2     list[SEQ];              // candidate (key, idx), index-ordered
    unsigned hist[256];
    unsigned memb[256];
    unsigned ws[8];
    float    red[8];
    unsigned Tkey;
    int      c_cnt, m_cnt, bb, wrem_s, ntot;
};

__global__ __launch_bounds__(256, 6) void topk_reduce_kernel(
    const float* __restrict__ simp, const float* __restrict__ simtp,
    const float* __restrict__ v1,  const float* __restrict__ v2,
    const unsigned char* __restrict__ v1m, const unsigned char* __restrict__ v2m,
    float* __restrict__ out1, float* __restrict__ out2) {
    __shared__ RSmem sm;
    const int t = threadIdx.x;
    const int r = blockIdx.x;
    const int b = blockIdx.y;
    const int z = blockIdx.z;

    const float* simbase      = z ? simtp : simp;
    const float* V            = z ? v1    : v2;
    const unsigned char* km   = z ? v1m   : v2m;
    const unsigned char* rmsk = z ? v2m   : v1m;
    float* out                = z ? out2  : out1;

    const float* srow = simbase + ((size_t)b * SEQ + r) * SEQ;
    const unsigned char* kmb = km + (size_t)b * SEQ;
    const int base = t * 8;

    // ---- load masked scores -> order-preserving keys (kept in registers)
    unsigned ky[8];
    float lm = -FLT_MAX;
    {
        float4 a0 = __ldcs((const float4*)(srow + base));
        float4 a1 = __ldcs((const float4*)(srow + base + 4));
        unsigned long long mk = *(const unsigned long long*)(kmb + base);
        float vv[8];
        vv[0] = a0.x; vv[1] = a0.y; vv[2] = a0.z; vv[3] = a0.w;
        vv[4] = a1.x; vv[5] = a1.y; vv[6] = a1.z; vv[7] = a1.w;
#pragma unroll
        for (int j = 0; j < 8; j++) {
            if ((mk >> (8 * j)) & 0xffull) vv[j] = -FLT_MAX;
            lm = fmaxf(lm, vv[j]);
            ky[j] = f2key(vv[j]);
        }
    }
    const float m = block_max_256(lm, sm.red);

    // ---- radix params from m
    unsigned kmin = f2key(m - 20.0f);   // tail below contributes <4e-6 rel denom
    int s;
    {
        unsigned W = f2key(m) - kmin;
        int bits = 32 - __clz(W | 1u);
        s = bits > 8 ? bits - 8 : 0;
    }

    sm.hist[t] = 0u;

    // ---- count candidates, scan for deterministic index-ordered append
    unsigned cnt = 0;
#pragma unroll
    for (int j = 0; j < 8; j++) cnt += (ky[j] >= kmin);
    unsigned pos = prefix_excl_256(cnt, sm.ws);   // leading sync publishes hist zero
    if (t == 255) sm.c_cnt = (int)(pos + cnt);
#pragma unroll
    for (int j = 0; j < 8; j++) {
        unsigned k = ky[j];
        if (k >= kmin) {
            sm.list[pos++] = make_int2((int)k, base + j);
            atomicAdd(&sm.hist[(k - kmin) >> s], 1u);
        }
    }
    __syncthreads();
    int c = sm.c_cnt;

    if (c < KTOP) {  // degenerate fallback: take all 2048 (exact)
        sm.hist[t] = 0u;
        __syncthreads();
        kmin = 0u; s = 24;
#pragma unroll
        for (int j = 0; j < 8; j++) {
            sm.list[base + j] = make_int2((int)ky[j], base + j);
            atomicAdd(&sm.hist[ky[j] >> 24], 1u);
        }
        __syncthreads();
        c = SEQ;
    }

    // ---- denom over candidates only
    float ld = 0.f;
    for (int i = t; i < c; i += 256)
        ld += __expf(key2f((unsigned)sm.list[i].x) - m);
    const float denom = block_sum_256(ld, sm.red);

    // ---- dynamic-range radix select: exact key T of the KTOP-th largest
    unsigned lo = kmin;
    int wrem = KTOP;
    unsigned T;
    while (true) {
        unsigned v  = sm.hist[t];
        unsigned se = suffix_excl_256(v, sm.ws);
        if (se < (unsigned)wrem && se + v >= (unsigned)wrem) {
            sm.bb     = t;
            sm.wrem_s = wrem - (int)se;
        }
        __syncthreads();
        lo  += ((unsigned)sm.bb) << s;
        wrem = sm.wrem_s;
        if (s == 0) { T = lo; break; }

        // boundary-window members (expected ~2)
        if (t == 0) sm.m_cnt = 0;
        __syncthreads();
        for (int i = t; i < c; i += 256) {
            unsigned k = (unsigned)sm.list[i].x;
            if (k >= lo && ((k - lo) >> s) == 0u) {
                int p = atomicAdd(&sm.m_cnt, 1);
                if (p < 256) sm.memb[p] = k;
            }
        }
        __syncthreads();
        const int mc = sm.m_cnt;
        if (mc <= 64) {
            if (t < 32) {
                for (int i = t; i < mc; i += 32) {
                    unsigned vv = sm.memb[i];
                    int rk = 0, eq = 0;
                    for (int j2 = 0; j2 < mc; j2++) {
                        rk += (sm.memb[j2] > vv);
                        eq += (sm.memb[j2] == vv);
                    }
                    if (rk < wrem && wrem <= rk + eq) sm.Tkey = vv;
                }
            }
            __syncthreads();
            T = sm.Tkey;
            break;
        }
        // rare refine
        {
            int snew = s > 8 ? s - 8 : 0;
            sm.hist[t] = 0u;
            __syncthreads();
            for (int i = t; i < c; i += 256) {
                unsigned k = (unsigned)sm.list[i].x;
                if (k >= lo && ((k - lo) >> s) == 0u)
                    atomicAdd(&sm.hist[(k - lo) >> snew], 1u);
            }
            s = snew;
            __syncthreads();
        }
    }

    // ---- selection from the candidate list (contiguous chunk per thread)
    const int cpt = (c + 255) >> 8;
    const int beg = min(t * cpt, c);
    const int end = min(beg + cpt, c);
    unsigned lgt = 0, leq = 0;
    for (int i = beg; i < end; i++) {
        unsigned k = (unsigned)sm.list[i].x;
        lgt += (k > T);
        leq += (k == T);
    }
    unsigned packed = (lgt << 16) | leq;
    unsigned pe = prefix_excl_256(packed, sm.ws);
    if (t == 255) sm.ntot = (int)(pe + packed);
    __syncthreads();
    const int ngt_tot  = sm.ntot >> 16;
    const int wrem_eq  = KTOP - ngt_tot;
    const int n        = min(KTOP, ngt_tot + (sm.ntot & 0xffff));
    {
        int g = (int)(pe >> 16);
        int e = (int)(pe & 0xffff);
        for (int i = beg; i < end; i++) {
            unsigned k = (unsigned)sm.list[i].x;
            if (k > T) {
                int p = g + min(e, wrem_eq);
                sm.sel[p] = make_int2(sm.list[i].y,
                                      __float_as_int(__expf(key2f(k) - m)));
                g++;
            } else if (k == T) {
                if (e < wrem_eq)
                    sm.sel[g + e] = make_int2(sm.list[i].y,
                                              __float_as_int(__expf(key2f(k) - m)));
                e++;
            }
        }
    }
    __syncthreads();

    // ---- gather: half-warp per selected row, independent float4 loads
    const float* Vb = V + (size_t)b * SEQ * DIM;
    const int lane = t & 31;
    const int w    = t >> 5;
    const int half = lane >> 4;
    const int li   = lane & 15;
    float4 acc = make_float4(0.f, 0.f, 0.f, 0.f);
#pragma unroll
    for (int it = 0; it < 8; it++) {
        const int j = it * 16 + w * 2 + half;
        if (j < n) {
            const int2  se2 = sm.sel[j];
            const float wgt = __int_as_float(se2.y);
            const float4 val = __ldg((const float4*)(Vb + (size_t)se2.x * DIM + li * 4));
            acc.x = fmaf(wgt, val.x, acc.x);
            acc.y = fmaf(wgt, val.y, acc.y);
            acc.z = fmaf(wgt, val.z, acc.z);
            acc.w = fmaf(wgt, val.w, acc.w);
        }
    }
    acc.x += __shfl_xor_sync(0xffffffffu, acc.x, 16);
    acc.y += __shfl_xor_sync(0xffffffffu, acc.y, 16);
    acc.z += __shfl_xor_sync(0xffffffffu, acc.z, 16);
    acc.w += __shfl_xor_sync(0xffffffffu, acc.w, 16);
    if (half == 0) *(float4*)&sm.wacc[w][li * 4] = acc;
    __syncthreads();
    if (t < 64) {
        float sacc = 0.f;
#pragma unroll
        for (int ww = 0; ww < 8; ww++) sacc += sm.wacc[ww][t];
        const bool rmk = rmsk[(size_t)b * SEQ + r] != 0;
        out[((size_t)b * SEQ + r) * DIM + t] = rmk ? 0.f : sacc * (1.f / denom);
    }
}

// ---------------------------------------------------------------------------
// Launch
// ---------------------------------------------------------------------------
extern "C" void kernel_launch(void* const* d_in, const int* in_sizes, int n_in,
                              void* d_out, int out_size) {
    const float*         v1  = (const float*)d_in[0];
    const unsigned char* v1m = (const unsigned char*)d_in[1];
    const float*         v2  = (const float*)d_in[2];
    const unsigned char* v2m = (const unsigned char*)d_in[3];
    float* out1 = (float*)d_out;
    float* out2 = out1 + (size_t)BATCH * SEQ * DIM;

    float* simp;  cudaGetSymbolAddress((void**)&simp,  g_sim);
    float* simtp; cudaGetSymbolAddress((void**)&simtp, g_simT);

    const int gemm_smem = 2 * 64 * 128 * (int)sizeof(float);  // 64 KB
    cudaFuncSetAttribute((const void*)gemm_kernel,
                         cudaFuncAttributeMaxDynamicSharedMemorySize, gemm_smem);

    dim3 gg(SEQ / 128, SEQ / 128, BATCH);
    gemm_kernel<<<gg, 256, gemm_smem>>>(v1, v2);

    dim3 gr(SEQ, BATCH, 2);
    topk_reduce_kernel<<<gr, 256>>>(simp, simtp, v1, v2, v1m, v2m, out1, out2);
}

// round 8
// speedup vs baseline: 1.2473x; 1.0463x over previous
#include <cuda_runtime.h>
#include <cuda_bf16.h>
#include <cfloat>
#include <cstdint>
#include <cstddef>

#define BATCH 16
#define SEQ   2048
#define DIM   64
#define KTOP  128

// 268 MB each: sim[b][q][k] and its transpose simT[b][k][q]
__device__ float g_sim [(size_t)BATCH * SEQ * SEQ];
__device__ float g_simT[(size_t)BATCH * SEQ * SEQ];

// Order-preserving float <-> uint key (larger float => larger key)
__device__ __forceinline__ unsigned f2key(float f) {
    unsigned u = __float_as_uint(f);
    return u ^ (((unsigned)((int)u >> 31)) | 0x80000000u);
}
__device__ __forceinline__ float key2f(unsigned k) {
    unsigned u = (k & 0x80000000u) ? (k ^ 0x80000000u) : ~k;
    return __uint_as_float(u);
}

// ---------------------------------------------------------------------------
// TF32x3 split-precision tensor-core GEMM.
// sim = v1 @ v2^T (and simT) with D = hiA*hiB + hiA*loB + loA*hiB.
// 128x128 tile, 256 threads (8 warps, 2m x 4n), warp tile 64x32,
// mma.sync.m16n8k8.tf32, K=64 in 8 k-steps.
// ---------------------------------------------------------------------------
#define GST 68   // smem row stride (floats): fragment LDS conflict-free

__device__ __forceinline__ void tf32split(float x, unsigned& hi, unsigned& lo) {
    unsigned h;
    asm("cvt.rna.tf32.f32 %0, %1;" : "=r"(h) : "f"(x));
    float r = x - __uint_as_float(h);
    unsigned l;
    asm("cvt.rna.tf32.f32 %0, %1;" : "=r"(l) : "f"(r));
    hi = h; lo = l;
}

#define MMA_TF32(d, A, B)                                                     \
    asm volatile("mma.sync.aligned.m16n8k8.row.col.f32.tf32.tf32.f32 "        \
                 "{%0,%1,%2,%3}, {%4,%5,%6,%7}, {%8,%9}, {%0,%1,%2,%3};"      \
                 : "+f"(d[0]), "+f"(d[1]), "+f"(d[2]), "+f"(d[3])             \
                 : "r"(A[0]), "r"(A[1]), "r"(A[2]), "r"(A[3]),                \
                   "r"(B[0]), "r"(B[1]))

__global__ __launch_bounds__(256, 1) void gemm_tf32_kernel(const float* __restrict__ v1,
                                                           const float* __restrict__ v2) {
    extern __shared__ float dsm[];
    float* AH = dsm;                    // [128][GST]
    float* AL = AH + 128 * GST;
    float* BH = AL + 128 * GST;
    float* BL = BH + 128 * GST;

    const int t  = threadIdx.x;
    const int b  = blockIdx.z;
    const int q0 = blockIdx.y * 128;
    const int k0 = blockIdx.x * 128;

    // ---- load tiles + tf32 hi/lo split (each element converted once)
    {
        const float* ap = v1 + ((size_t)b * SEQ + q0) * DIM;
        const float* bp = v2 + ((size_t)b * SEQ + k0) * DIM;
#pragma unroll
        for (int i = 0; i < 8; i++) {
            const int e   = t + i * 256;       // float4 id (2048 per tensor)
            const int row = e >> 4;
            const int c   = (e & 15) * 4;
            float4 x = *(const float4*)(ap + row * DIM + c);
            float4 y = *(const float4*)(bp + row * DIM + c);
            unsigned h0, l0, h1, l1, h2, l2, h3, l3;
            tf32split(x.x, h0, l0); tf32split(x.y, h1, l1);
            tf32split(x.z, h2, l2); tf32split(x.w, h3, l3);
            AH[row * GST + c + 0] = __uint_as_float(h0);
            AH[row * GST + c + 1] = __uint_as_float(h1);
            AH[row * GST + c + 2] = __uint_as_float(h2);
            AH[row * GST + c + 3] = __uint_as_float(h3);
            AL[row * GST + c + 0] = __uint_as_float(l0);
            AL[row * GST + c + 1] = __uint_as_float(l1);
            AL[row * GST + c + 2] = __uint_as_float(l2);
            AL[row * GST + c + 3] = __uint_as_float(l3);
            tf32split(y.x, h0, l0); tf32split(y.y, h1, l1);
            tf32split(y.z, h2, l2); tf32split(y.w, h3, l3);
            BH[row * GST + c + 0] = __uint_as_float(h0);
            BH[row * GST + c + 1] = __uint_as_float(h1);
            BH[row * GST + c + 2] = __uint_as_float(h2);
            BH[row * GST + c + 3] = __uint_as_float(h3);
            BL[row * GST + c + 0] = __uint_as_float(l0);
            BL[row * GST + c + 1] = __uint_as_float(l1);
            BL[row * GST + c + 2] = __uint_as_float(l2);
            BL[row * GST + c + 3] = __uint_as_float(l3);
        }
    }
    __syncthreads();

    const int lane = t & 31;
    const int w    = t >> 5;
    const int wm   = w & 1;            // 2 warps over M
    const int wn   = w >> 1;           // 4 warps over N
    const int gid  = lane >> 2;
    const int tig  = lane & 3;

    float acc[4][4][4];
#pragma unroll
    for (int i = 0; i < 4; i++)
#pragma unroll
        for (int j = 0; j < 4; j++)
#pragma unroll
            for (int k = 0; k < 4; k++) acc[i][j][k] = 0.f;

    const int r0 = wm * 64 + gid;
    const int n0 = wn * 32 + gid;

#pragma unroll
    for (int ks = 0; ks < 8; ks++) {
        const int c0 = ks * 8 + tig;
        unsigned ah[4][4], al[4][4], bh[4][2], bl[4][2];
#pragma unroll
        for (int tm = 0; tm < 4; tm++) {
            const int r = r0 + tm * 16;
            ah[tm][0] = __float_as_uint(AH[r * GST + c0]);
            ah[tm][1] = __float_as_uint(AH[(r + 8) * GST + c0]);
            ah[tm][2] = __float_as_uint(AH[r * GST + c0 + 4]);
            ah[tm][3] = __float_as_uint(AH[(r + 8) * GST + c0 + 4]);
            al[tm][0] = __float_as_uint(AL[r * GST + c0]);
            al[tm][1] = __float_as_uint(AL[(r + 8) * GST + c0]);
            al[tm][2] = __float_as_uint(AL[r * GST + c0 + 4]);
            al[tm][3] = __float_as_uint(AL[(r + 8) * GST + c0 + 4]);
        }
#pragma unroll
        for (int tn = 0; tn < 4; tn++) {
            const int n = n0 + tn * 8;
            bh[tn][0] = __float_as_uint(BH[n * GST + c0]);
            bh[tn][1] = __float_as_uint(BH[n * GST + c0 + 4]);
            bl[tn][0] = __float_as_uint(BL[n * GST + c0]);
            bl[tn][1] = __float_as_uint(BL[n * GST + c0 + 4]);
        }
#pragma unroll
        for (int tm = 0; tm < 4; tm++)
#pragma unroll
            for (int tn = 0; tn < 4; tn++) {
                MMA_TF32(acc[tm][tn], ah[tm], bh[tn]);
                MMA_TF32(acc[tm][tn], ah[tm], bl[tn]);
                MMA_TF32(acc[tm][tn], al[tm], bh[tn]);
            }
    }

    // ---- epilogue: stage through smem (reuse), coalesced stores of sim & simT
    __syncthreads();
    float* Ts = dsm;                   // [128][129] = 66 KB <= 139 KB
#pragma unroll
    for (int tm = 0; tm < 4; tm++)
#pragma unroll
        for (int tn = 0; tn < 4; tn++) {
            const int rr = wm * 64 + tm * 16 + gid;
            const int cc = wn * 32 + tn * 8 + tig * 2;
            Ts[rr * 129 + cc]           = acc[tm][tn][0];
            Ts[rr * 129 + cc + 1]       = acc[tm][tn][1];
            Ts[(rr + 8) * 129 + cc]     = acc[tm][tn][2];
            Ts[(rr + 8) * 129 + cc + 1] = acc[tm][tn][3];
        }
    __syncthreads();
#pragma unroll
    for (int i = 0; i < 16; i++) {
        const int e   = t + i * 256;   // 4096 float4
        const int row = e >> 5;
        const int c4  = (e & 31) * 4;
        float4 o;
        o.x = Ts[row * 129 + c4];
        o.y = Ts[row * 129 + c4 + 1];
        o.z = Ts[row * 129 + c4 + 2];
        o.w = Ts[row * 129 + c4 + 3];
        *(float4*)(g_sim + ((size_t)b * SEQ + q0 + row) * SEQ + k0 + c4) = o;
    }
#pragma unroll
    for (int i = 0; i < 16; i++) {
        const int e  = t + i * 256;
        const int kr = e >> 5;
        const int q4 = (e & 31) * 4;
        float4 o;
        o.x = Ts[q4 * 129 + kr];
        o.y = Ts[(q4 + 1) * 129 + kr];
        o.z = Ts[(q4 + 2) * 129 + kr];
        o.w = Ts[(q4 + 3) * 129 + kr];
        *(float4*)(g_simT + ((size_t)b * SEQ + k0 + kr) * SEQ + q0 + q4) = o;
    }
}

// ---------------------------------------------------------------------------
// Block helpers (256 threads)
// ---------------------------------------------------------------------------
__device__ __forceinline__ unsigned suffix_excl_256(unsigned v, unsigned* ws) {
    __syncthreads();
    const int lane = threadIdx.x & 31;
    unsigned s = v;
#pragma unroll
    for (int o = 1; o < 32; o <<= 1) {
        unsigned n = __shfl_down_sync(0xffffffffu, s, o);
        if (lane + o < 32) s += n;
    }
    if (lane == 0) ws[threadIdx.x >> 5] = s;
    __syncthreads();
    unsigned cross = 0;
    const int w = threadIdx.x >> 5;
#pragma unroll
    for (int i = 0; i < 8; i++)
        if (i > w) cross += ws[i];
    return cross + (s - v);
}

__device__ __forceinline__ unsigned prefix_excl_256(unsigned v, unsigned* ws) {
    __syncthreads();
    const int lane = threadIdx.x & 31;
    unsigned s = v;
#pragma unroll
    for (int o = 1; o < 32; o <<= 1) {
        unsigned n = __shfl_up_sync(0xffffffffu, s, o);
        if (lane - o >= 0) s += n;
    }
    if (lane == 31) ws[threadIdx.x >> 5] = s;
    __syncthreads();
    unsigned cross = 0;
    const int w = threadIdx.x >> 5;
#pragma unroll
    for (int i = 0; i < 8; i++)
        if (i < w) cross += ws[i];
    return cross + (s - v);
}

__device__ __forceinline__ float block_max_256(float v, float* red) {
    __syncthreads();
#pragma unroll
    for (int o = 16; o > 0; o >>= 1) v = fmaxf(v, __shfl_xor_sync(0xffffffffu, v, o));
    if ((threadIdx.x & 31) == 0) red[threadIdx.x >> 5] = v;
    __syncthreads();
    return fmaxf(fmaxf(fmaxf(red[0], red[1]), fmaxf(red[2], red[3])),
                 fmaxf(fmaxf(red[4], red[5]), fmaxf(red[6], red[7])));
}

__device__ __forceinline__ float block_sum_256(float v, float* red) {
    __syncthreads();
#pragma unroll
    for (int o = 16; o > 0; o >>= 1) v += __shfl_xor_sync(0xffffffffu, v, o);
    if ((threadIdx.x & 31) == 0) red[threadIdx.x >> 5] = v;
    __syncthreads();
    return ((red[0] + red[1]) + (red[2] + red[3])) + ((red[4] + red[5]) + (red[6] + red[7]));
}

// ---------------------------------------------------------------------------
// Row top-k softmax reduce (unchanged from R7, measured 544 us).
// ---------------------------------------------------------------------------
struct RSmem {
    alignas(16) float wacc[8][64];
    alignas(16) int2  sel[KTOP];
    int2     list[SEQ];
    unsigned hist[256];
    unsigned memb[256];
    unsigned ws[8];
    float    red[8];
    unsigned Tkey;
    int      c_cnt, m_cnt, bb, wrem_s, ntot;
};

__global__ __launch_bounds__(256, 6) void topk_reduce_kernel(
    const float* __restrict__ simp, const float* __restrict__ simtp,
    const float* __restrict__ v1,  const float* __restrict__ v2,
    const unsigned char* __restrict__ v1m, const unsigned char* __restrict__ v2m,
    float* __restrict__ out1, float* __restrict__ out2) {
    __shared__ RSmem sm;
    const int t = threadIdx.x;
    const int r = blockIdx.x;
    const int b = blockIdx.y;
    const int z = blockIdx.z;

    const float* simbase      = z ? simtp : simp;
    const float* V            = z ? v1    : v2;
    const unsigned char* km   = z ? v1m   : v2m;
    const unsigned char* rmsk = z ? v2m   : v1m;
    float* out                = z ? out2  : out1;

    const float* srow = simbase + ((size_t)b * SEQ + r) * SEQ;
    const unsigned char* kmb = km + (size_t)b * SEQ;
    const int base = t * 8;

    unsigned ky[8];
    float lm = -FLT_MAX;
    {
        float4 a0 = __ldcs((const float4*)(srow + base));
        float4 a1 = __ldcs((const float4*)(srow + base + 4));
        unsigned long long mk = *(const unsigned long long*)(kmb + base);
        float vv[8];
        vv[0] = a0.x; vv[1] = a0.y; vv[2] = a0.z; vv[3] = a0.w;
        vv[4] = a1.x; vv[5] = a1.y; vv[6] = a1.z; vv[7] = a1.w;
#pragma unroll
        for (int j = 0; j < 8; j++) {
            if ((mk >> (8 * j)) & 0xffull) vv[j] = -FLT_MAX;
            lm = fmaxf(lm, vv[j]);
            ky[j] = f2key(vv[j]);
        }
    }
    const float m = block_max_256(lm, sm.red);

    unsigned kmin = f2key(m - 20.0f);
    int s;
    {
        unsigned W = f2key(m) - kmin;
        int bits = 32 - __clz(W | 1u);
        s = bits > 8 ? bits - 8 : 0;
    }

    sm.hist[t] = 0u;

    unsigned cnt = 0;
#pragma unroll
    for (int j = 0; j < 8; j++) cnt += (ky[j] >= kmin);
    unsigned pos = prefix_excl_256(cnt, sm.ws);
    if (t == 255) sm.c_cnt = (int)(pos + cnt);
#pragma unroll
    for (int j = 0; j < 8; j++) {
        unsigned k = ky[j];
        if (k >= kmin) {
            sm.list[pos++] = make_int2((int)k, base + j);
            atomicAdd(&sm.hist[(k - kmin) >> s], 1u);
        }
    }
    __syncthreads();
    int c = sm.c_cnt;

    if (c < KTOP) {
        sm.hist[t] = 0u;
        __syncthreads();
        kmin = 0u; s = 24;
#pragma unroll
        for (int j = 0; j < 8; j++) {
            sm.list[base + j] = make_int2((int)ky[j], base + j);
            atomicAdd(&sm.hist[ky[j] >> 24], 1u);
        }
        __syncthreads();
        c = SEQ;
    }

    float ld = 0.f;
    for (int i = t; i < c; i += 256)
        ld += __expf(key2f((unsigned)sm.list[i].x) - m);
    const float denom = block_sum_256(ld, sm.red);

    unsigned lo = kmin;
    int wrem = KTOP;
    unsigned T;
    while (true) {
        unsigned v  = sm.hist[t];
        unsigned se = suffix_excl_256(v, sm.ws);
        if (se < (unsigned)wrem && se + v >= (unsigned)wrem) {
            sm.bb     = t;
            sm.wrem_s = wrem - (int)se;
        }
        __syncthreads();
        lo  += ((unsigned)sm.bb) << s;
        wrem = sm.wrem_s;
        if (s == 0) { T = lo; break; }

        if (t == 0) sm.m_cnt = 0;
        __syncthreads();
        for (int i = t; i < c; i += 256) {
            unsigned k = (unsigned)sm.list[i].x;
            if (k >= lo && ((k - lo) >> s) == 0u) {
                int p = atomicAdd(&sm.m_cnt, 1);
                if (p < 256) sm.memb[p] = k;
            }
        }
        __syncthreads();
        const int mc = sm.m_cnt;
        if (mc <= 64) {
            if (t < 32) {
                for (int i = t; i < mc; i += 32) {
                    unsigned vv = sm.memb[i];
                    int rk = 0, eq = 0;
                    for (int j2 = 0; j2 < mc; j2++) {
                        rk += (sm.memb[j2] > vv);
                        eq += (sm.memb[j2] == vv);
                    }
                    if (rk < wrem && wrem <= rk + eq) sm.Tkey = vv;
                }
            }
            __syncthreads();
            T = sm.Tkey;
            break;
        }
        {
            int snew = s > 8 ? s - 8 : 0;
            sm.hist[t] = 0u;
            __syncthreads();
            for (int i = t; i < c; i += 256) {
                unsigned k = (unsigned)sm.list[i].x;
                if (k >= lo && ((k - lo) >> s) == 0u)
                    atomicAdd(&sm.hist[(k - lo) >> snew], 1u);
            }
            s = snew;
            __syncthreads();
        }
    }

    const int cpt = (c + 255) >> 8;
    const int beg = min(t * cpt, c);
    const int end = min(beg + cpt, c);
    unsigned lgt = 0, leq = 0;
    for (int i = beg; i < end; i++) {
        unsigned k = (unsigned)sm.list[i].x;
        lgt += (k > T);
        leq += (k == T);
    }
    unsigned packed = (lgt << 16) | leq;
    unsigned pe = prefix_excl_256(packed, sm.ws);
    if (t == 255) sm.ntot = (int)(pe + packed);
    __syncthreads();
    const int ngt_tot  = sm.ntot >> 16;
    const int wrem_eq  = KTOP - ngt_tot;
    const int n        = min(KTOP, ngt_tot + (sm.ntot & 0xffff));
    {
        int g = (int)(pe >> 16);
        int e = (int)(pe & 0xffff);
        for (int i = beg; i < end; i++) {
            unsigned k = (unsigned)sm.list[i].x;
            if (k > T) {
                int p = g + min(e, wrem_eq);
                sm.sel[p] = make_int2(sm.list[i].y,
                                      __float_as_int(__expf(key2f(k) - m)));
                g++;
            } else if (k == T) {
                if (e < wrem_eq)
                    sm.sel[g + e] = make_int2(sm.list[i].y,
                                              __float_as_int(__expf(key2f(k) - m)));
                e++;
            }
        }
    }
    __syncthreads();

    const float* Vb = V + (size_t)b * SEQ * DIM;
    const int lane = t & 31;
    const int w    = t >> 5;
    const int half = lane >> 4;
    const int li   = lane & 15;
    float4 acc = make_float4(0.f, 0.f, 0.f, 0.f);
#pragma unroll
    for (int it = 0; it < 8; it++) {
        const int j = it * 16 + w * 2 + half;
        if (j < n) {
            const int2  se2 = sm.sel[j];
            const float wgt = __int_as_float(se2.y);
            const float4 val = __ldg((const float4*)(Vb + (size_t)se2.x * DIM + li * 4));
            acc.x = fmaf(wgt, val.x, acc.x);
            acc.y = fmaf(wgt, val.y, acc.y);
            acc.z = fmaf(wgt, val.z, acc.z);
            acc.w = fmaf(wgt, val.w, acc.w);
        }
    }
    acc.x += __shfl_xor_sync(0xffffffffu, acc.x, 16);
    acc.y += __shfl_xor_sync(0xffffffffu, acc.y, 16);
    acc.z += __shfl_xor_sync(0xffffffffu, acc.z, 16);
    acc.w += __shfl_xor_sync(0xffffffffu, acc.w, 16);
    if (half == 0) *(float4*)&sm.wacc[w][li * 4] = acc;
    __syncthreads();
    if (t < 64) {
        float sacc = 0.f;
#pragma unroll
        for (int ww = 0; ww < 8; ww++) sacc += sm.wacc[ww][t];
        const bool rmk = rmsk[(size_t)b * SEQ + r] != 0;
        out[((size_t)b * SEQ + r) * DIM + t] = rmk ? 0.f : sacc * (1.f / denom);
    }
}

// ---------------------------------------------------------------------------
// Launch
// ---------------------------------------------------------------------------
extern "C" void kernel_launch(void* const* d_in, const int* in_sizes, int n_in,
                              void* d_out, int out_size) {
    const float*         v1  = (const float*)d_in[0];
    const unsigned char* v1m = (const unsigned char*)d_in[1];
    const float*         v2  = (const float*)d_in[2];
    const unsigned char* v2m = (const unsigned char*)d_in[3];
    float* out1 = (float*)d_out;
    float* out2 = out1 + (size_t)BATCH * SEQ * DIM;

    float* simp;  cudaGetSymbolAddress((void**)&simp,  g_sim);
    float* simtp; cudaGetSymbolAddress((void**)&simtp, g_simT);

    const int gemm_smem = 4 * 128 * GST * (int)sizeof(float);  // 139264 B
    cudaFuncSetAttribute((const void*)gemm_tf32_kernel,
                         cudaFuncAttributeMaxDynamicSharedMemorySize, gemm_smem);

    dim3 gg(SEQ / 128, SEQ / 128, BATCH);
    gemm_tf32_kernel<<<gg, 256, gemm_smem>>>(v1, v2);

    dim3 gr(SEQ, BATCH, 2);
    topk_reduce_kernel<<<gr, 256>>>(simp, simtp, v1, v2, v1m, v2m, out1, out2);
}

// round 9
// speedup vs baseline: 1.4443x; 1.1579x over previous
#include <cuda_runtime.h>
#include <cuda_bf16.h>
#include <cfloat>
#include <cstdint>
#include <cstddef>

#define BATCH 16
#define SEQ   2048
#define DIM   64
#define KTOP  128

// 268 MB each: sim[b][q][k] and its transpose simT[b][k][q]
__device__ float g_sim [(size_t)BATCH * SEQ * SEQ];
__device__ float g_simT[(size_t)BATCH * SEQ * SEQ];

// Order-preserving float <-> uint key (larger float => larger key)
__device__ __forceinline__ unsigned f2key(float f) {
    unsigned u = __float_as_uint(f);
    return u ^ (((unsigned)((int)u >> 31)) | 0x80000000u);
}
__device__ __forceinline__ float key2f(unsigned k) {
    unsigned u = (k & 0x80000000u) ? (k ^ 0x80000000u) : ~k;
    return __uint_as_float(u);
}

// ---------------------------------------------------------------------------
// TF32x3 tensor-core GEMM, tile 128(M) x 64(N), 2 blocks/SM.
// sim = v1 @ v2^T ; simT stored directly from fragments (sector-coalesced).
// ---------------------------------------------------------------------------
#define GST 68   // smem row stride (floats): fragment LDS conflict-free

__device__ __forceinline__ void tf32split(float x, unsigned& hi, unsigned& lo) {
    unsigned h;
    asm("cvt.rna.tf32.f32 %0, %1;" : "=r"(h) : "f"(x));
    float r = x - __uint_as_float(h);
    unsigned l;
    asm("cvt.rna.tf32.f32 %0, %1;" : "=r"(l) : "f"(r));
    hi = h; lo = l;
}

#define MMA_TF32(d, A, B)                                                     \
    asm volatile("mma.sync.aligned.m16n8k8.row.col.f32.tf32.tf32.f32 "        \
                 "{%0,%1,%2,%3}, {%4,%5,%6,%7}, {%8,%9}, {%0,%1,%2,%3};"      \
                 : "+f"(d[0]), "+f"(d[1]), "+f"(d[2]), "+f"(d[3])             \
                 : "r"(A[0]), "r"(A[1]), "r"(A[2]), "r"(A[3]),                \
                   "r"(B[0]), "r"(B[1]))

__global__ __launch_bounds__(256, 2) void gemm_tf32_kernel(const float* __restrict__ v1,
                                                           const float* __restrict__ v2) {
    extern __shared__ float dsm[];
    float* AH = dsm;                    // [128][GST]
    float* AL = AH + 128 * GST;         // [128][GST]
    float* BH = AL + 128 * GST;         // [64][GST]
    float* BL = BH + 64 * GST;          // [64][GST]

    const int t  = threadIdx.x;
    const int b  = blockIdx.z;
    const int q0 = blockIdx.y * 128;
    const int k0 = blockIdx.x * 64;

    // ---- load tiles + tf32 hi/lo split
    {
        const float* ap = v1 + ((size_t)b * SEQ + q0) * DIM;
#pragma unroll
        for (int i = 0; i < 8; i++) {
            const int e   = t + i * 256;      // 2048 float4 (A: 128x64)
            const int row = e >> 4;
            const int c   = (e & 15) * 4;
            float4 x = *(const float4*)(ap + row * DIM + c);
            unsigned h0, l0, h1, l1, h2, l2, h3, l3;
            tf32split(x.x, h0, l0); tf32split(x.y, h1, l1);
            tf32split(x.z, h2, l2); tf32split(x.w, h3, l3);
            *(float4*)&AH[row * GST + c] = make_float4(__uint_as_float(h0), __uint_as_float(h1),
                                                       __uint_as_float(h2), __uint_as_float(h3));
            *(float4*)&AL[row * GST + c] = make_float4(__uint_as_float(l0), __uint_as_float(l1),
                                                       __uint_as_float(l2), __uint_as_float(l3));
        }
        const float* bp = v2 + ((size_t)b * SEQ + k0) * DIM;
#pragma unroll
        for (int i = 0; i < 4; i++) {
            const int e   = t + i * 256;      // 1024 float4 (B: 64x64)
            const int row = e >> 4;
            const int c   = (e & 15) * 4;
            float4 y = *(const float4*)(bp + row * DIM + c);
            unsigned h0, l0, h1, l1, h2, l2, h3, l3;
            tf32split(y.x, h0, l0); tf32split(y.y, h1, l1);
            tf32split(y.z, h2, l2); tf32split(y.w, h3, l3);
            *(float4*)&BH[row * GST + c] = make_float4(__uint_as_float(h0), __uint_as_float(h1),
                                                       __uint_as_float(h2), __uint_as_float(h3));
            *(float4*)&BL[row * GST + c] = make_float4(__uint_as_float(l0), __uint_as_float(l1),
                                                       __uint_as_float(l2), __uint_as_float(l3));
        }
    }
    __syncthreads();

    const int lane = t & 31;
    const int w    = t >> 5;
    const int wm   = w & 3;            // 4 warps over M (32 rows each)
    const int wn   = w >> 2;           // 2 warps over N (32 cols each)
    const int gid  = lane >> 2;
    const int tig  = lane & 3;

    float acc[2][4][4];
#pragma unroll
    for (int i = 0; i < 2; i++)
#pragma unroll
        for (int j = 0; j < 4; j++)
#pragma unroll
            for (int k = 0; k < 4; k++) acc[i][j][k] = 0.f;

    const int r0 = wm * 32 + gid;
    const int n0 = wn * 32 + gid;

#pragma unroll
    for (int ks = 0; ks < 8; ks++) {
        const int c0 = ks * 8 + tig;
        unsigned ah[2][4], al[2][4], bh[4][2], bl[4][2];
#pragma unroll
        for (int tm = 0; tm < 2; tm++) {
            const int r = r0 + tm * 16;
            ah[tm][0] = __float_as_uint(AH[r * GST + c0]);
            ah[tm][1] = __float_as_uint(AH[(r + 8) * GST + c0]);
            ah[tm][2] = __float_as_uint(AH[r * GST + c0 + 4]);
            ah[tm][3] = __float_as_uint(AH[(r + 8) * GST + c0 + 4]);
            al[tm][0] = __float_as_uint(AL[r * GST + c0]);
            al[tm][1] = __float_as_uint(AL[(r + 8) * GST + c0]);
            al[tm][2] = __float_as_uint(AL[r * GST + c0 + 4]);
            al[tm][3] = __float_as_uint(AL[(r + 8) * GST + c0 + 4]);
        }
#pragma unroll
        for (int tn = 0; tn < 4; tn++) {
            const int n = n0 + tn * 8;
            bh[tn][0] = __float_as_uint(BH[n * GST + c0]);
            bh[tn][1] = __float_as_uint(BH[n * GST + c0 + 4]);
            bl[tn][0] = __float_as_uint(BL[n * GST + c0]);
            bl[tn][1] = __float_as_uint(BL[n * GST + c0 + 4]);
        }
        // three split passes, 8-MMA dependency distance for ILP
#pragma unroll
        for (int tm = 0; tm < 2; tm++)
#pragma unroll
            for (int tn = 0; tn < 4; tn++) MMA_TF32(acc[tm][tn], ah[tm], bh[tn]);
#pragma unroll
        for (int tm = 0; tm < 2; tm++)
#pragma unroll
            for (int tn = 0; tn < 4; tn++) MMA_TF32(acc[tm][tn], ah[tm], bl[tn]);
#pragma unroll
        for (int tm = 0; tm < 2; tm++)
#pragma unroll
            for (int tn = 0; tn < 4; tn++) MMA_TF32(acc[tm][tn], al[tm], bh[tn]);
    }

    // ---- direct stores: every warp store covers full 32B sectors
#pragma unroll
    for (int tm = 0; tm < 2; tm++)
#pragma unroll
        for (int tn = 0; tn < 4; tn++) {
            const int rr = q0 + wm * 32 + tm * 16 + gid;
            const int cc = k0 + wn * 32 + tn * 8 + tig * 2;
            *(float2*)&g_sim[((size_t)b * SEQ + rr) * SEQ + cc] =
                make_float2(acc[tm][tn][0], acc[tm][tn][1]);
            *(float2*)&g_sim[((size_t)b * SEQ + rr + 8) * SEQ + cc] =
                make_float2(acc[tm][tn][2], acc[tm][tn][3]);
            g_simT[((size_t)b * SEQ + cc) * SEQ + rr]         = acc[tm][tn][0];
            g_simT[((size_t)b * SEQ + cc + 1) * SEQ + rr]     = acc[tm][tn][1];
            g_simT[((size_t)b * SEQ + cc) * SEQ + rr + 8]     = acc[tm][tn][2];
            g_simT[((size_t)b * SEQ + cc + 1) * SEQ + rr + 8] = acc[tm][tn][3];
        }
}

// ---------------------------------------------------------------------------
// Block helpers (256 threads)
// ---------------------------------------------------------------------------
__device__ __forceinline__ unsigned suffix_excl_256(unsigned v, unsigned* ws) {
    __syncthreads();
    const int lane = threadIdx.x & 31;
    unsigned s = v;
#pragma unroll
    for (int o = 1; o < 32; o <<= 1) {
        unsigned n = __shfl_down_sync(0xffffffffu, s, o);
        if (lane + o < 32) s += n;
    }
    if (lane == 0) ws[threadIdx.x >> 5] = s;
    __syncthreads();
    unsigned cross = 0;
    const int w = threadIdx.x >> 5;
#pragma unroll
    for (int i = 0; i < 8; i++)
        if (i > w) cross += ws[i];
    return cross + (s - v);
}

__device__ __forceinline__ unsigned prefix_excl_256(unsigned v, unsigned* ws) {
    __syncthreads();
    const int lane = threadIdx.x & 31;
    unsigned s = v;
#pragma unroll
    for (int o = 1; o < 32; o <<= 1) {
        unsigned n = __shfl_up_sync(0xffffffffu, s, o);
        if (lane - o >= 0) s += n;
    }
    if (lane == 31) ws[threadIdx.x >> 5] = s;
    __syncthreads();
    unsigned cross = 0;
    const int w = threadIdx.x >> 5;
#pragma unroll
    for (int i = 0; i < 8; i++)
        if (i < w) cross += ws[i];
    return cross + (s - v);
}

__device__ __forceinline__ float block_max_256(float v, float* red) {
    __syncthreads();
#pragma unroll
    for (int o = 16; o > 0; o >>= 1) v = fmaxf(v, __shfl_xor_sync(0xffffffffu, v, o));
    if ((threadIdx.x & 31) == 0) red[threadIdx.x >> 5] = v;
    __syncthreads();
    return fmaxf(fmaxf(fmaxf(red[0], red[1]), fmaxf(red[2], red[3])),
                 fmaxf(fmaxf(red[4], red[5]), fmaxf(red[6], red[7])));
}

__device__ __forceinline__ float block_sum_256(float v, float* red) {
    __syncthreads();
#pragma unroll
    for (int o = 16; o > 0; o >>= 1) v += __shfl_xor_sync(0xffffffffu, v, o);
    if ((threadIdx.x & 31) == 0) red[threadIdx.x >> 5] = v;
    __syncthreads();
    return ((red[0] + red[1]) + (red[2] + red[3])) + ((red[4] + red[5]) + (red[6] + red[7]));
}

// ---------------------------------------------------------------------------
// Row top-k softmax reduce. One block per (b, row, dir).
// Keys register-resident; no candidate list; denom exact over all 2048.
// ---------------------------------------------------------------------------
struct RSmem {
    alignas(16) float wacc[8][64];
    alignas(16) int2  sel[KTOP];       // (idx, weight bits)
    unsigned hist[256];
    unsigned memb[256];
    unsigned ws[8];
    float    red[8];
    unsigned Tkey;
    int      m_cnt, bb, wrem_s, ntot, seltot;
};

__global__ __launch_bounds__(256, 6) void topk_reduce_kernel(
    const float* __restrict__ simp, const float* __restrict__ simtp,
    const float* __restrict__ v1,  const float* __restrict__ v2,
    const unsigned char* __restrict__ v1m, const unsigned char* __restrict__ v2m,
    float* __restrict__ out1, float* __restrict__ out2) {
    __shared__ RSmem sm;
    const int t = threadIdx.x;
    const int r = blockIdx.x;
    const int b = blockIdx.y;
    const int z = blockIdx.z;

    const float* simbase      = z ? simtp : simp;
    const float* V            = z ? v1    : v2;
    const unsigned char* km   = z ? v1m   : v2m;
    const unsigned char* rmsk = z ? v2m   : v1m;
    float* out                = z ? out2  : out1;

    const float* srow = simbase + ((size_t)b * SEQ + r) * SEQ;
    const unsigned char* kmb = km + (size_t)b * SEQ;
    const int base = t * 8;

    // ---- load masked scores -> keys (registers only)
    unsigned ky[8];
    float lm = -FLT_MAX;
    {
        float4 a0 = __ldcs((const float4*)(srow + base));
        float4 a1 = __ldcs((const float4*)(srow + base + 4));
        unsigned long long mk = *(const unsigned long long*)(kmb + base);
        float vv[8];
        vv[0] = a0.x; vv[1] = a0.y; vv[2] = a0.z; vv[3] = a0.w;
        vv[4] = a1.x; vv[5] = a1.y; vv[6] = a1.z; vv[7] = a1.w;
#pragma unroll
        for (int j = 0; j < 8; j++) {
            if ((mk >> (8 * j)) & 0xffull) vv[j] = -FLT_MAX;
            lm = fmaxf(lm, vv[j]);
            ky[j] = f2key(vv[j]);
        }
    }
    sm.hist[t] = 0u;
    const float m = block_max_256(lm, sm.red);   // syncs publish hist zero

    unsigned kmin = f2key(m - 20.0f);   // hist range only; denom stays exact
    int s;
    {
        unsigned W = f2key(m) - kmin;
        int bits = 32 - __clz(W | 1u);
        s = bits > 8 ? bits - 8 : 0;
    }

    // ---- exact denom over all 2048 + histogram of in-range keys (fused)
    float ld = 0.f;
#pragma unroll
    for (int j = 0; j < 8; j++) {
        unsigned k = ky[j];
        ld += __expf(key2f(k) - m);
        if (k >= kmin) atomicAdd(&sm.hist[(k - kmin) >> s], 1u);
    }
    const float denom = block_sum_256(ld, sm.red);  // publishes hist

    // ---- dynamic-range radix select: exact key T of the KTOP-th largest
    unsigned lo = kmin;
    int wrem = KTOP;
    unsigned T;
    while (true) {
        unsigned v  = sm.hist[t];
        unsigned se = suffix_excl_256(v, sm.ws);
        if (t == 0) sm.ntot = (int)(se + v);
        if (se < (unsigned)wrem && se + v >= (unsigned)wrem) {
            sm.bb     = t;
            sm.wrem_s = wrem - (int)se;
        }
        __syncthreads();
        if (sm.ntot < wrem) {           // rare: widen to full key range
            sm.hist[t] = 0u;
            __syncthreads();
            lo = 0u; s = 24;
#pragma unroll
            for (int j = 0; j < 8; j++) atomicAdd(&sm.hist[ky[j] >> 24], 1u);
            __syncthreads();
            continue;
        }
        lo  += ((unsigned)sm.bb) << s;
        wrem = sm.wrem_s;
        if (s == 0) { T = lo; break; }

        // collect boundary-window members from registers (expected ~2)
        if (t == 0) sm.m_cnt = 0;
        __syncthreads();
#pragma unroll
        for (int j = 0; j < 8; j++) {
            unsigned k = ky[j];
            if (k >= lo && ((k - lo) >> s) == 0u) {
                int p = atomicAdd(&sm.m_cnt, 1);
                if (p < 256) sm.memb[p] = k;
            }
        }
        __syncthreads();
        const int mc = sm.m_cnt;
        if (mc <= 64) {
            if (t < 32) {
                for (int i = t; i < mc; i += 32) {
                    unsigned vv = sm.memb[i];
                    int rk = 0, eq = 0;
                    for (int j2 = 0; j2 < mc; j2++) {
                        rk += (sm.memb[j2] > vv);
                        eq += (sm.memb[j2] == vv);
                    }
                    if (rk < wrem && wrem <= rk + eq) sm.Tkey = vv;
                }
            }
            __syncthreads();
            T = sm.Tkey;
            break;
        }
        // rare: refine window with finer bins
        {
            int snew = s > 8 ? s - 8 : 0;
            sm.hist[t] = 0u;
            __syncthreads();
#pragma unroll
            for (int j = 0; j < 8; j++) {
                unsigned k = ky[j];
                if (k >= lo && ((k - lo) >> s) == 0u)
                    atomicAdd(&sm.hist[(k - lo) >> snew], 1u);
            }
            s = snew;
            __syncthreads();
        }
    }

    // ---- selection from registers: keys > T, then == T in index order
    unsigned fgt = 0, feq = 0;
    unsigned lgt = 0, leq = 0;
#pragma unroll
    for (int j = 0; j < 8; j++) {
        unsigned k = ky[j];
        if (k > T)       { fgt |= (1u << j); lgt++; }
        else if (k == T) { feq |= (1u << j); leq++; }
    }
    unsigned packed = (lgt << 16) | leq;
    unsigned pe = prefix_excl_256(packed, sm.ws);
    if (t == 255) sm.seltot = (int)(pe + packed);
    __syncthreads();
    const int ngt_tot = sm.seltot >> 16;
    const int wrem_eq = KTOP - ngt_tot;
    const int n       = min(KTOP, ngt_tot + (sm.seltot & 0xffff));
    {
        int g = (int)(pe >> 16);
        int e = (int)(pe & 0xffff);
#pragma unroll
        for (int j = 0; j < 8; j++) {
            unsigned k = ky[j];
            if (fgt & (1u << j)) {
                sm.sel[g + min(e, wrem_eq)] =
                    make_int2(base + j, __float_as_int(__expf(key2f(k) - m)));
                g++;
            } else if (feq & (1u << j)) {
                if (e < wrem_eq)
                    sm.sel[g + e] =
                        make_int2(base + j, __float_as_int(__expf(key2f(k) - m)));
                e++;
            }
        }
    }
    __syncthreads();

    // ---- gather: half-warp per selected row, independent float4 loads
    const float* Vb = V + (size_t)b * SEQ * DIM;
    const int lane = t & 31;
    const int w    = t >> 5;
    const int half = lane >> 4;
    const int li   = lane & 15;
    float4 acc = make_float4(0.f, 0.f, 0.f, 0.f);
#pragma unroll
    for (int it = 0; it < 8; it++) {
        const int j = it * 16 + w * 2 + half;
        if (j < n) {
            const int2  se2 = sm.sel[j];
            const float wgt = __int_as_float(se2.y);
            const float4 val = __ldg((const float4*)(Vb + (size_t)se2.x * DIM + li * 4));
            acc.x = fmaf(wgt, val.x, acc.x);
            acc.y = fmaf(wgt, val.y, acc.y);
            acc.z = fmaf(wgt, val.z, acc.z);
            acc.w = fmaf(wgt, val.w, acc.w);
        }
    }
    acc.x += __shfl_xor_sync(0xffffffffu, acc.x, 16);
    acc.y += __shfl_xor_sync(0xffffffffu, acc.y, 16);
    acc.z += __shfl_xor_sync(0xffffffffu, acc.z, 16);
    acc.w += __shfl_xor_sync(0xffffffffu, acc.w, 16);
    if (half == 0) *(float4*)&sm.wacc[w][li * 4] = acc;
    __syncthreads();
    if (t < 64) {
        float sacc = 0.f;
#pragma unroll
        for (int ww = 0; ww < 8; ww++) sacc += sm.wacc[ww][t];
        const bool rmk = rmsk[(size_t)b * SEQ + r] != 0;
        out[((size_t)b * SEQ + r) * DIM + t] = rmk ? 0.f : sacc * (1.f / denom);
    }
}

// ---------------------------------------------------------------------------
// Launch
// ---------------------------------------------------------------------------
extern "C" void kernel_launch(void* const* d_in, const int* in_sizes, int n_in,
                              void* d_out, int out_size) {
    const float*         v1  = (const float*)d_in[0];
    const unsigned char* v1m = (const unsigned char*)d_in[1];
    const float*         v2  = (const float*)d_in[2];
    const unsigned char* v2m = (const unsigned char*)d_in[3];
    float* out1 = (float*)d_out;
    float* out2 = out1 + (size_t)BATCH * SEQ * DIM;

    float* simp;  cudaGetSymbolAddress((void**)&simp,  g_sim);
    float* simtp; cudaGetSymbolAddress((void**)&simtp, g_simT);

    const int gemm_smem = (128 + 128 + 64 + 64) * GST * (int)sizeof(float);  // 104448 B
    cudaFuncSetAttribute((const void*)gemm_tf32_kernel,
                         cudaFuncAttributeMaxDynamicSharedMemorySize, gemm_smem);

    dim3 gg(SEQ / 64, SEQ / 128, BATCH);
    gemm_tf32_kernel<<<gg, 256, gemm_smem>>>(v1, v2);

    dim3 gr(SEQ, BATCH, 2);
    topk_reduce_kernel<<<gr, 256>>>(simp, simtp, v1, v2, v1m, v2m, out1, out2);
}